// round 1
// baseline (speedup 1.0000x reference)
#include <cuda_runtime.h>
#include <cstdint>
#include <cstddef>

// Problem constants (fixed shapes for this dataset problem)
#define NN   50000
#define EE   800000
#define BB   2
#define MTOT (BB*NN)      // 100000 rows for GEMMs
#define ETOT (EE+NN)      // 850000 edges incl. self-loops
#define F0   216
#define F1   64
#define F2   8
#define F3   3
#define BN_EPS 1e-5f

#define OUT_OFF_OUT 0
#define OUT_OFF_X1  (MTOT*F3)   // 300000

// ---------------- device scratch (static; no allocations) ----------------
__device__ int   g_flag;               // 1 => edge_index stored as int32, 0 => int64
__device__ int   g_row[ETOT];
__device__ int   g_col[ETOT];
__device__ int   g_cnt[NN];
__device__ int   g_rowptr[NN + 1];
__device__ int   g_woff[NN];
__device__ float g_dinv[NN];
__device__ int   g_srow[ETOT];
__device__ float g_snorm[ETOT];
__device__ float g_xw1[(size_t)MTOT * F1];
__device__ float g_h1 [(size_t)MTOT * F1];
__device__ float g_xw2[(size_t)MTOT * F2];
__device__ float g_xw3[(size_t)MTOT * F3];
__device__ float g_stat1[2 * F1];      // sums, sumsq
__device__ float g_st1 [2 * F1];       // s, t  (BN affine fold)
__device__ float g_stat2[2 * F2];
__device__ float g_st2 [2 * F2];

// ---------------- K0: zero counters / flag / stats ----------------
__global__ void k_zero() {
    int i = blockIdx.x * blockDim.x + threadIdx.x;
    for (int j = i; j < NN; j += gridDim.x * blockDim.x) g_cnt[j] = 0;
    if (i == 0) g_flag = 0;
    if (i < 2 * F1) g_stat1[i] = 0.f;
    if (i < 2 * F2) g_stat2[i] = 0.f;
}

// ---------------- K1: detect edge_index dtype ----------------
// If int64: words at odd positions over the first 2*EE words are all zero
// (values in [0, 50000)). If int32: those words are actual random indices.
__global__ void k_detect(const unsigned int* __restrict__ w) {
    int i = blockIdx.x * blockDim.x + threadIdx.x;
    for (int e = i; e < EE; e += gridDim.x * blockDim.x) {
        if (w[2 * e + 1] != 0u) { g_flag = 1; return; }
    }
}

// ---------------- K2: build raw row/col (+self loops) and degree histogram ----------------
__global__ void k_build(const void* __restrict__ ei) {
    int i = blockIdx.x * blockDim.x + threadIdx.x;
    int f = g_flag;
    const int*       e32 = (const int*)ei;
    const long long* e64 = (const long long*)ei;
    for (int e = i; e < ETOT; e += gridDim.x * blockDim.x) {
        int r, c;
        if (e < EE) {
            if (f) { r = e32[e]; c = e32[EE + e]; }
            else   { r = (int)e64[e]; c = (int)e64[EE + e]; }
        } else {
            r = c = e - EE;
        }
        g_row[e] = r; g_col[e] = c;
        atomicAdd(&g_cnt[c], 1);
    }
}

// ---------------- K3: single-block exclusive scan -> rowptr/woff, dinv ----------------
__global__ void k_scan() {
    const int T = 1024;
    const int CH = (NN + T - 1) / T;
    __shared__ int ssum[T];
    int tid = threadIdx.x;
    int base = tid * CH;
    int s = 0;
    for (int j = 0; j < CH; j++) {
        int idx = base + j;
        if (idx < NN) s += g_cnt[idx];
    }
    ssum[tid] = s;
    __syncthreads();
    for (int off = 1; off < T; off <<= 1) {
        int v = (tid >= off) ? ssum[tid - off] : 0;
        __syncthreads();
        ssum[tid] += v;
        __syncthreads();
    }
    int run = ssum[tid] - s;  // exclusive prefix for this chunk
    for (int j = 0; j < CH; j++) {
        int idx = base + j;
        if (idx < NN) {
            int c = g_cnt[idx];
            g_rowptr[idx] = run;
            g_woff[idx]   = run;
            g_dinv[idx]   = rsqrtf((float)c);  // deg >= 1 always (self-loop)
            run += c;
        }
    }
    if (tid == T - 1) g_rowptr[NN] = ssum[T - 1];
}

// ---------------- K4: scatter into CSR with fused norm ----------------
__global__ void k_scatter() {
    int i = blockIdx.x * blockDim.x + threadIdx.x;
    for (int e = i; e < ETOT; e += gridDim.x * blockDim.x) {
        int r = g_row[e], c = g_col[e];
        int p = atomicAdd(&g_woff[c], 1);
        g_srow[p]  = r;
        g_snorm[p] = g_dinv[r] * g_dinv[c];
    }
}

// ---------------- K5: GEMM1  [MTOT,216] @ [216,64] -> g_xw1 ----------------
__global__ void __launch_bounds__(256) k_gemm1(const float* __restrict__ A,
                                               const float* __restrict__ W) {
    __shared__ float As[8][64];
    __shared__ float Bs[8][64];
    int tid  = threadIdx.x;
    int row0 = blockIdx.x * 64;

    int lm = tid >> 2;          // 0..63   (A row within tile)
    int lk = (tid & 3) * 2;     // 0,2,4,6 (A k pair)
    int wk = tid >> 5;          // 0..7    (B k)
    int wn = (tid & 31) * 2;    // 0..62   (B n pair)
    int tm = (tid & 15) * 4;
    int tn = (tid >> 4) * 4;

    int arow = row0 + lm;
    bool avalid = arow < MTOT;
    const float* aptr = A + (size_t)arow * F0 + lk;

    float acc[4][4];
#pragma unroll
    for (int i = 0; i < 4; i++)
#pragma unroll
        for (int j = 0; j < 4; j++) acc[i][j] = 0.f;

    for (int k0 = 0; k0 < F0; k0 += 8) {
        float2 a = avalid ? *(const float2*)(aptr + k0) : make_float2(0.f, 0.f);
        As[lk][lm] = a.x;
        As[lk + 1][lm] = a.y;
        *(float2*)&Bs[wk][wn] = *(const float2*)(W + (size_t)(k0 + wk) * F1 + wn);
        __syncthreads();
#pragma unroll
        for (int kk = 0; kk < 8; kk++) {
            float4 av = *(const float4*)&As[kk][tm];
            float4 bv = *(const float4*)&Bs[kk][tn];
            acc[0][0] += av.x * bv.x; acc[0][1] += av.x * bv.y; acc[0][2] += av.x * bv.z; acc[0][3] += av.x * bv.w;
            acc[1][0] += av.y * bv.x; acc[1][1] += av.y * bv.y; acc[1][2] += av.y * bv.z; acc[1][3] += av.y * bv.w;
            acc[2][0] += av.z * bv.x; acc[2][1] += av.z * bv.y; acc[2][2] += av.z * bv.z; acc[2][3] += av.z * bv.w;
            acc[3][0] += av.w * bv.x; acc[3][1] += av.w * bv.y; acc[3][2] += av.w * bv.z; acc[3][3] += av.w * bv.w;
        }
        __syncthreads();
    }
#pragma unroll
    for (int i = 0; i < 4; i++) {
        int r = row0 + tm + i;
        if (r < MTOT) {
            float4 o = make_float4(acc[i][0], acc[i][1], acc[i][2], acc[i][3]);
            *(float4*)&g_xw1[(size_t)r * F1 + tn] = o;
        }
    }
}

// ---------------- K6: prop1 (F=64,B=2), fused +b1, ReLU -> g_h1 ----------------
__global__ void __launch_bounds__(256) k_prop1(const float* __restrict__ b1) {
    int gwarp = (blockIdx.x * blockDim.x + threadIdx.x) >> 5;
    int lane  = threadIdx.x & 31;
    if (gwarp >= NN) return;
    int start = g_rowptr[gwarp], end = g_rowptr[gwarp + 1];
    int b  = lane >> 4;
    int c4 = (lane & 15) * 4;
    const float* src = g_xw1 + (size_t)b * NN * F1 + c4;
    float4 acc = make_float4(0.f, 0.f, 0.f, 0.f);
    for (int e = start; e < end; e++) {
        int   r = g_srow[e];
        float w = g_snorm[e];
        float4 v = *(const float4*)(src + (size_t)r * F1);
        acc.x += w * v.x; acc.y += w * v.y; acc.z += w * v.z; acc.w += w * v.w;
    }
    float4 bb = *(const float4*)(b1 + c4);
    acc.x = fmaxf(acc.x + bb.x, 0.f);
    acc.y = fmaxf(acc.y + bb.y, 0.f);
    acc.z = fmaxf(acc.z + bb.z, 0.f);
    acc.w = fmaxf(acc.w + bb.w, 0.f);
    *(float4*)(g_h1 + (size_t)(b * NN + gwarp) * F1 + c4) = acc;
}

// ---------------- K7: per-channel stats over g_h1 ----------------
__global__ void __launch_bounds__(256) k_stats1() {
    int tid = threadIdx.x;
    float s = 0.f, sq = 0.f;
    size_t total = (size_t)MTOT * F1;
    for (size_t i = (size_t)blockIdx.x * blockDim.x + tid; i < total;
         i += (size_t)gridDim.x * blockDim.x) {
        float v = g_h1[i];
        s += v; sq += v * v;
    }
    __shared__ float sh[256], shq[256];
    sh[tid] = s; shq[tid] = sq;
    __syncthreads();
    if (tid < 128) { sh[tid] += sh[tid + 128]; shq[tid] += shq[tid + 128]; }
    __syncthreads();
    if (tid < 64) {
        float fs = sh[tid] + sh[tid + 64];
        float fq = shq[tid] + shq[tid + 64];
        atomicAdd(&g_stat1[tid], fs);
        atomicAdd(&g_stat1[F1 + tid], fq);
    }
}

__global__ void k_params1(const float* __restrict__ g, const float* __restrict__ be) {
    int c = threadIdx.x;
    if (c < F1) {
        float inv = 1.0f / (float)MTOT;
        float mean = g_stat1[c] * inv;
        float var  = g_stat1[F1 + c] * inv - mean * mean;
        float rstd = rsqrtf(var + BN_EPS);
        float s = g[c] * rstd;
        g_st1[c]      = s;
        g_st1[F1 + c] = be[c] - mean * s;
    }
}

// ---------------- K9: GEMM2 with fused BN affine: (h*s+t) @ W2 -> g_xw2 ----------------
__global__ void __launch_bounds__(256) k_gemm2(const float* __restrict__ W2) {
    __shared__ float tile[32][64];
    __shared__ float w2s[F1 * F2];
    __shared__ float ss[F1], tt[F1];
    int tid = threadIdx.x;
    if (tid < F1) { ss[tid] = g_st1[tid]; tt[tid] = g_st1[F1 + tid]; }
    w2s[tid] = W2[tid];
    w2s[tid + 256] = W2[tid + 256];
    __syncthreads();

    int row0 = blockIdx.x * 32;
    for (int i = tid; i < 32 * 64; i += 256) {
        int r = i >> 6, k = i & 63;
        float v = (row0 + r < MTOT) ? g_h1[(size_t)(row0 + r) * F1 + k] : 0.f;
        tile[r][k] = v * ss[k] + tt[k];
    }
    __syncthreads();

    int r = tid >> 3, c = tid & 7;
    float acc = 0.f;
#pragma unroll
    for (int k = 0; k < F1; k++) acc += tile[r][k] * w2s[k * F2 + c];
    if (row0 + r < MTOT) g_xw2[(size_t)(row0 + r) * F2 + c] = acc;
}

// ---------------- K10: prop2 (F=8,B=2), +b2 -> x1 (output region) ----------------
__global__ void __launch_bounds__(256) k_prop2(const float* __restrict__ b2,
                                               float* __restrict__ x1out) {
    int gt = blockIdx.x * blockDim.x + threadIdx.x;
    int node = gt >> 4;
    if (node >= NN) return;
    int sub = gt & 15;
    int b = sub >> 3, c = sub & 7;
    int start = g_rowptr[node], end = g_rowptr[node + 1];
    const float* src = g_xw2 + (size_t)b * NN * F2 + c;
    float acc = 0.f;
    for (int e = start; e < end; e++) {
        acc += g_snorm[e] * src[(size_t)g_srow[e] * F2];
    }
    acc += b2[c];
    x1out[(size_t)(b * NN + node) * F2 + c] = acc;
}

// ---------------- K11: stats over relu(x1) ----------------
__global__ void __launch_bounds__(256) k_stats2(const float* __restrict__ x1) {
    int tid = threadIdx.x;
    float s = 0.f, sq = 0.f;
    size_t total = (size_t)MTOT * F2;
    for (size_t i = (size_t)blockIdx.x * blockDim.x + tid; i < total;
         i += (size_t)gridDim.x * blockDim.x) {
        float v = fmaxf(x1[i], 0.f);
        s += v; sq += v * v;
    }
    __shared__ float sh[256], shq[256];
    sh[tid] = s; shq[tid] = sq;
    __syncthreads();
    for (int off = 128; off >= 8; off >>= 1) {
        if (tid < off) { sh[tid] += sh[tid + off]; shq[tid] += shq[tid + off]; }
        __syncthreads();
    }
    if (tid < F2) {
        atomicAdd(&g_stat2[tid], sh[tid]);
        atomicAdd(&g_stat2[F2 + tid], shq[tid]);
    }
}

__global__ void k_params2(const float* __restrict__ g, const float* __restrict__ be) {
    int c = threadIdx.x;
    if (c < F2) {
        float inv = 1.0f / (float)MTOT;
        float mean = g_stat2[c] * inv;
        float var  = g_stat2[F2 + c] * inv - mean * mean;
        float rstd = rsqrtf(var + BN_EPS);
        float s = g[c] * rstd;
        g_st2[c]      = s;
        g_st2[F2 + c] = be[c] - mean * s;
    }
}

// ---------------- K13: GEMM3: (relu(x1)*s+t) @ W3 -> g_xw3 ----------------
__global__ void __launch_bounds__(256) k_gemm3(const float* __restrict__ x1,
                                               const float* __restrict__ W3) {
    __shared__ float w3s[F2 * F3];
    __shared__ float s2[F2], t2[F2];
    int tid = threadIdx.x;
    if (tid < F2 * F3) w3s[tid] = W3[tid];
    if (tid < F2) { s2[tid] = g_st2[tid]; t2[tid] = g_st2[F2 + tid]; }
    __syncthreads();

    int row = blockIdx.x * blockDim.x + tid;
    if (row < MTOT) {
        float v[F2];
        float4 a = *(const float4*)(x1 + (size_t)row * F2);
        float4 b = *(const float4*)(x1 + (size_t)row * F2 + 4);
        v[0] = a.x; v[1] = a.y; v[2] = a.z; v[3] = a.w;
        v[4] = b.x; v[5] = b.y; v[6] = b.z; v[7] = b.w;
#pragma unroll
        for (int k = 0; k < F2; k++) v[k] = fmaxf(v[k], 0.f) * s2[k] + t2[k];
        float o0 = 0.f, o1 = 0.f, o2 = 0.f;
#pragma unroll
        for (int k = 0; k < F2; k++) {
            o0 += v[k] * w3s[k * F3 + 0];
            o1 += v[k] * w3s[k * F3 + 1];
            o2 += v[k] * w3s[k * F3 + 2];
        }
        g_xw3[(size_t)row * F3 + 0] = o0;
        g_xw3[(size_t)row * F3 + 1] = o1;
        g_xw3[(size_t)row * F3 + 2] = o2;
    }
}

// ---------------- K14: prop3 (F=3,B=2), +b3 -> out (output region) ----------------
__global__ void __launch_bounds__(256) k_prop3(const float* __restrict__ b3,
                                               float* __restrict__ out) {
    int gt = blockIdx.x * blockDim.x + threadIdx.x;
    int node = gt >> 3;
    int sub = gt & 7;
    int b = sub >> 2, c = sub & 3;
    if (node >= NN || c >= F3) return;
    int start = g_rowptr[node], end = g_rowptr[node + 1];
    const float* src = g_xw3 + (size_t)b * NN * F3 + c;
    float acc = 0.f;
    for (int e = start; e < end; e++) {
        acc += g_snorm[e] * src[(size_t)g_srow[e] * F3];
    }
    acc += b3[c];
    out[(size_t)(b * NN + node) * F3 + c] = acc;
}

// ---------------- host launcher ----------------
extern "C" void kernel_launch(void* const* d_in, const int* in_sizes, int n_in,
                              void* d_out, int out_size) {
    const float* x   = (const float*)d_in[0];
    const float* W1  = (const float*)d_in[1];
    const float* b1  = (const float*)d_in[2];
    const float* g1  = (const float*)d_in[3];
    const float* be1 = (const float*)d_in[4];
    const float* W2  = (const float*)d_in[5];
    const float* b2  = (const float*)d_in[6];
    const float* g2  = (const float*)d_in[7];
    const float* be2 = (const float*)d_in[8];
    const float* W3  = (const float*)d_in[9];
    const float* b3  = (const float*)d_in[10];
    const void*  ei  = d_in[11];

    float* out_p = (float*)d_out + OUT_OFF_OUT;
    float* x1_p  = (float*)d_out + OUT_OFF_X1;

    // graph prep
    k_zero<<<256, 256>>>();
    k_detect<<<1024, 256>>>((const unsigned int*)ei);
    k_build<<<1024, 256>>>(ei);
    k_scan<<<1, 1024>>>();
    k_scatter<<<1024, 256>>>();

    // layer 1
    k_gemm1<<<(MTOT + 63) / 64, 256>>>(x, W1);
    k_prop1<<<(NN * 32 + 255) / 256, 256>>>(b1);
    k_stats1<<<512, 256>>>();
    k_params1<<<1, 64>>>(g1, be1);

    // layer 2
    k_gemm2<<<(MTOT + 31) / 32, 256>>>(W2);
    k_prop2<<<(NN * 16 + 255) / 256, 256>>>(b2, x1_p);
    k_stats2<<<256, 256>>>(x1_p);
    k_params2<<<1, 32>>>(g2, be2);

    // layer 3
    k_gemm3<<<(MTOT + 255) / 256, 256>>>(x1_p, W3);
    k_prop3<<<(NN * 8 + 255) / 256, 256>>>(b3, out_p);
}

// round 2
// speedup vs baseline: 1.3538x; 1.3538x over previous
#include <cuda_runtime.h>
#include <cstdint>
#include <cstddef>

#define NN   50000
#define EE   800000
#define BB   2
#define MTOT (BB*NN)      // 100000
#define ETOT (EE+NN)      // 850000
#define F0   216
#define F1   64
#define F2   8
#define F3   3
#define BN_EPS 1e-5f

#define OUT_OFF_OUT 0
#define OUT_OFF_X1  (MTOT*F3)   // 300000

#define SCAN_B 256
#define NBLK   ((NN + SCAN_B - 1) / SCAN_B)   // 196

// ---------------- device scratch ----------------
__device__ int   g_flag;               // 1 => int32 edge_index, 0 => int64
__device__ int   g_cnt[NN];
__device__ int   g_rowptr[NN + 1];
__device__ int   g_woff[NN];
__device__ float g_dinv[NN];
__device__ int   g_bsum[NBLK];
__device__ int   g_boff[NBLK];
__device__ int   g_srow[ETOT];
__device__ float g_snorm[ETOT];
__device__ float g_xw1[(size_t)MTOT * F1];
__device__ float g_h1 [(size_t)MTOT * F1];
__device__ float g_xw2[(size_t)MTOT * F2];
__device__ float g_xw3[(size_t)MTOT * F3];
__device__ float g_stat1[2 * F1];
__device__ float g_st1 [2 * F1];
__device__ float g_stat2[2 * F2];
__device__ float g_st2 [2 * F2];

// ---------------- K0: zero ----------------
__global__ void k_zero() {
    int i = blockIdx.x * blockDim.x + threadIdx.x;
    for (int j = i; j < NN; j += gridDim.x * blockDim.x) g_cnt[j] = 0;
    if (i == 0) g_flag = 0;
    if (i < 2 * F1) g_stat1[i] = 0.f;
    if (i < 2 * F2) g_stat2[i] = 0.f;
}

// ---------------- K1: dtype detect (int64 high words all zero since idx<50000) ----
__global__ void k_detect(const unsigned int* __restrict__ w) {
    int i = blockIdx.x * blockDim.x + threadIdx.x;
    for (int e = i; e < EE; e += gridDim.x * blockDim.x) {
        if (w[2 * e + 1] != 0u) { g_flag = 1; return; }
    }
}

// ---------------- K2: degree histogram (direct from edge_index) ----------------
__global__ void k_build(const void* __restrict__ ei) {
    int i = blockIdx.x * blockDim.x + threadIdx.x;
    int f = g_flag;
    const int*       e32 = (const int*)ei;
    const long long* e64 = (const long long*)ei;
    for (int e = i; e < ETOT; e += gridDim.x * blockDim.x) {
        int c;
        if (e < EE) c = f ? e32[EE + e] : (int)e64[EE + e];
        else        c = e - EE;
        atomicAdd(&g_cnt[c], 1);
    }
}

// ---------------- scan: 3-kernel two-level ----------------
__global__ void k_scan_a() {
    __shared__ int sh[SCAN_B];
    int tid = threadIdx.x;
    int idx = blockIdx.x * SCAN_B + tid;
    sh[tid] = (idx < NN) ? g_cnt[idx] : 0;
    __syncthreads();
    for (int off = 128; off > 0; off >>= 1) {
        if (tid < off) sh[tid] += sh[tid + off];
        __syncthreads();
    }
    if (tid == 0) g_bsum[blockIdx.x] = sh[0];
}

__global__ void k_scan_b() {
    __shared__ int sh[SCAN_B];
    int tid = threadIdx.x;
    int v = (tid < NBLK) ? g_bsum[tid] : 0;
    sh[tid] = v;
    __syncthreads();
    for (int off = 1; off < SCAN_B; off <<= 1) {
        int t = (tid >= off) ? sh[tid - off] : 0;
        __syncthreads();
        sh[tid] += t;
        __syncthreads();
    }
    if (tid < NBLK) g_boff[tid] = sh[tid] - v;   // exclusive
}

__global__ void k_scan_c() {
    __shared__ int sh[SCAN_B];
    int tid = threadIdx.x;
    int idx = blockIdx.x * SCAN_B + tid;
    int cnt = (idx < NN) ? g_cnt[idx] : 0;
    sh[tid] = cnt;
    __syncthreads();
    for (int off = 1; off < SCAN_B; off <<= 1) {
        int t = (tid >= off) ? sh[tid - off] : 0;
        __syncthreads();
        sh[tid] += t;
        __syncthreads();
    }
    int off0 = g_boff[blockIdx.x] + sh[tid] - cnt;  // exclusive global prefix
    if (idx < NN) {
        g_rowptr[idx] = off0;
        g_woff[idx]   = off0;
        g_dinv[idx]   = rsqrtf((float)cnt);          // deg>=1 (self loop)
        if (idx == NN - 1) g_rowptr[NN] = off0 + cnt;
    }
}

// ---------------- K4: scatter into CSR with fused norm ----------------
__global__ void k_scatter(const void* __restrict__ ei) {
    int i = blockIdx.x * blockDim.x + threadIdx.x;
    int f = g_flag;
    const int*       e32 = (const int*)ei;
    const long long* e64 = (const long long*)ei;
    for (int e = i; e < ETOT; e += gridDim.x * blockDim.x) {
        int r, c;
        if (e < EE) {
            if (f) { r = e32[e]; c = e32[EE + e]; }
            else   { r = (int)e64[e]; c = (int)e64[EE + e]; }
        } else {
            r = c = e - EE;
        }
        int p = atomicAdd(&g_woff[c], 1);
        g_srow[p]  = r;
        g_snorm[p] = g_dinv[r] * g_dinv[c];
    }
}

// ---------------- K5: GEMM1 [MTOT,216]@[216,64] -> g_xw1 ----------------
__global__ void __launch_bounds__(256) k_gemm1(const float* __restrict__ A,
                                               const float* __restrict__ W) {
    __shared__ float As[8][64];
    __shared__ float Bs[8][64];
    int tid  = threadIdx.x;
    int row0 = blockIdx.x * 64;

    int lm = tid >> 2;
    int lk = (tid & 3) * 2;
    int wk = tid >> 5;
    int wn = (tid & 31) * 2;
    int tm = (tid & 15) * 4;
    int tn = (tid >> 4) * 4;

    int arow = row0 + lm;
    bool avalid = arow < MTOT;
    const float* aptr = A + (size_t)arow * F0 + lk;

    float acc[4][4];
#pragma unroll
    for (int i = 0; i < 4; i++)
#pragma unroll
        for (int j = 0; j < 4; j++) acc[i][j] = 0.f;

    for (int k0 = 0; k0 < F0; k0 += 8) {
        float2 a = avalid ? *(const float2*)(aptr + k0) : make_float2(0.f, 0.f);
        As[lk][lm] = a.x;
        As[lk + 1][lm] = a.y;
        *(float2*)&Bs[wk][wn] = *(const float2*)(W + (size_t)(k0 + wk) * F1 + wn);
        __syncthreads();
#pragma unroll
        for (int kk = 0; kk < 8; kk++) {
            float4 av = *(const float4*)&As[kk][tm];
            float4 bv = *(const float4*)&Bs[kk][tn];
            acc[0][0] += av.x * bv.x; acc[0][1] += av.x * bv.y; acc[0][2] += av.x * bv.z; acc[0][3] += av.x * bv.w;
            acc[1][0] += av.y * bv.x; acc[1][1] += av.y * bv.y; acc[1][2] += av.y * bv.z; acc[1][3] += av.y * bv.w;
            acc[2][0] += av.z * bv.x; acc[2][1] += av.z * bv.y; acc[2][2] += av.z * bv.z; acc[2][3] += av.z * bv.w;
            acc[3][0] += av.w * bv.x; acc[3][1] += av.w * bv.y; acc[3][2] += av.w * bv.z; acc[3][3] += av.w * bv.w;
        }
        __syncthreads();
    }
#pragma unroll
    for (int i = 0; i < 4; i++) {
        int r = row0 + tm + i;
        if (r < MTOT) {
            float4 o = make_float4(acc[i][0], acc[i][1], acc[i][2], acc[i][3]);
            *(float4*)&g_xw1[(size_t)r * F1 + tn] = o;
        }
    }
}

// ---------------- K6: prop1 (F=64,B=2) + bias + ReLU + fused BN stats ----------------
// grid = NN/8 = 6250 blocks exactly, 8 warps/block, 1 warp per node.
__global__ void __launch_bounds__(256) k_prop1(const float* __restrict__ b1) {
    __shared__ float ssum[F1];
    __shared__ float ssq [F1];
    int tid = threadIdx.x;
    if (tid < F1) { ssum[tid] = 0.f; ssq[tid] = 0.f; }
    __syncthreads();

    int gwarp = (blockIdx.x * blockDim.x + tid) >> 5;   // node id, always < NN
    int lane  = tid & 31;
    int start = g_rowptr[gwarp], end = g_rowptr[gwarp + 1];
    int b  = lane >> 4;
    int c4 = (lane & 15) * 4;
    const float* src = g_xw1 + (size_t)b * NN * F1 + c4;
    float4 acc = make_float4(0.f, 0.f, 0.f, 0.f);
    for (int e = start; e < end; e++) {
        int   r = g_srow[e];
        float w = g_snorm[e];
        float4 v = *(const float4*)(src + (size_t)r * F1);
        acc.x += w * v.x; acc.y += w * v.y; acc.z += w * v.z; acc.w += w * v.w;
    }
    float4 bb = *(const float4*)(b1 + c4);
    acc.x = fmaxf(acc.x + bb.x, 0.f);
    acc.y = fmaxf(acc.y + bb.y, 0.f);
    acc.z = fmaxf(acc.z + bb.z, 0.f);
    acc.w = fmaxf(acc.w + bb.w, 0.f);
    *(float4*)(g_h1 + (size_t)(b * NN + gwarp) * F1 + c4) = acc;

    // fused BN stats: combine the two batch halves (lane ^ 16 has same channels)
    float s0 = acc.x, s1 = acc.y, s2 = acc.z, s3 = acc.w;
    float q0 = s0 * s0, q1 = s1 * s1, q2 = s2 * s2, q3 = s3 * s3;
    s0 += __shfl_xor_sync(0xffffffffu, s0, 16);
    s1 += __shfl_xor_sync(0xffffffffu, s1, 16);
    s2 += __shfl_xor_sync(0xffffffffu, s2, 16);
    s3 += __shfl_xor_sync(0xffffffffu, s3, 16);
    q0 += __shfl_xor_sync(0xffffffffu, q0, 16);
    q1 += __shfl_xor_sync(0xffffffffu, q1, 16);
    q2 += __shfl_xor_sync(0xffffffffu, q2, 16);
    q3 += __shfl_xor_sync(0xffffffffu, q3, 16);
    if (lane < 16) {
        atomicAdd(&ssum[c4 + 0], s0); atomicAdd(&ssq[c4 + 0], q0);
        atomicAdd(&ssum[c4 + 1], s1); atomicAdd(&ssq[c4 + 1], q1);
        atomicAdd(&ssum[c4 + 2], s2); atomicAdd(&ssq[c4 + 2], q2);
        atomicAdd(&ssum[c4 + 3], s3); atomicAdd(&ssq[c4 + 3], q3);
    }
    __syncthreads();
    if (tid < F1) {
        atomicAdd(&g_stat1[tid], ssum[tid]);
        atomicAdd(&g_stat1[F1 + tid], ssq[tid]);
    }
}

__global__ void k_params1(const float* __restrict__ g, const float* __restrict__ be) {
    int c = threadIdx.x;
    if (c < F1) {
        float inv = 1.0f / (float)MTOT;
        float mean = g_stat1[c] * inv;
        float var  = g_stat1[F1 + c] * inv - mean * mean;
        float rstd = rsqrtf(var + BN_EPS);
        float s = g[c] * rstd;
        g_st1[c]      = s;
        g_st1[F1 + c] = be[c] - mean * s;
    }
}

// ---------------- K9: GEMM2 with fused BN affine ----------------
__global__ void __launch_bounds__(256) k_gemm2(const float* __restrict__ W2) {
    __shared__ float tile[32][64];
    __shared__ float w2s[F1 * F2];
    __shared__ float ss[F1], tt[F1];
    int tid = threadIdx.x;
    if (tid < F1) { ss[tid] = g_st1[tid]; tt[tid] = g_st1[F1 + tid]; }
    w2s[tid] = W2[tid];
    w2s[tid + 256] = W2[tid + 256];
    __syncthreads();

    int row0 = blockIdx.x * 32;
    for (int i = tid; i < 32 * 64; i += 256) {
        int r = i >> 6, k = i & 63;
        float v = (row0 + r < MTOT) ? g_h1[(size_t)(row0 + r) * F1 + k] : 0.f;
        tile[r][k] = v * ss[k] + tt[k];
    }
    __syncthreads();

    int r = tid >> 3, c = tid & 7;
    float acc = 0.f;
#pragma unroll
    for (int k = 0; k < F1; k++) acc += tile[r][k] * w2s[k * F2 + c];
    if (row0 + r < MTOT) g_xw2[(size_t)(row0 + r) * F2 + c] = acc;
}

// ---------------- K10: prop2 (F=8,B=2) + bias -> x1, fused stats over relu(x1) ----
// grid = NN*16/256 = 3125 blocks exactly.
__global__ void __launch_bounds__(256) k_prop2(const float* __restrict__ b2,
                                               float* __restrict__ x1out) {
    __shared__ float ssum[F2];
    __shared__ float ssq [F2];
    int tid = threadIdx.x;
    if (tid < F2) { ssum[tid] = 0.f; ssq[tid] = 0.f; }
    __syncthreads();

    int gt = blockIdx.x * blockDim.x + tid;
    int node = gt >> 4;
    int sub = gt & 15;
    int b = sub >> 3, c = sub & 7;
    int start = g_rowptr[node], end = g_rowptr[node + 1];
    const float* src = g_xw2 + (size_t)b * NN * F2 + c;
    float acc = 0.f;
    for (int e = start; e < end; e++) {
        acc += g_snorm[e] * src[(size_t)g_srow[e] * F2];
    }
    acc += b2[c];
    x1out[(size_t)(b * NN + node) * F2 + c] = acc;

    // stats over relu(x1): lanes with same (b,c) differ by xor 16 (node) and xor 8 (batch)
    float v = fmaxf(acc, 0.f);
    float q = v * v;
    v += __shfl_xor_sync(0xffffffffu, v, 16);
    q += __shfl_xor_sync(0xffffffffu, q, 16);
    v += __shfl_xor_sync(0xffffffffu, v, 8);
    q += __shfl_xor_sync(0xffffffffu, q, 8);
    if ((tid & 31) < 8) {
        atomicAdd(&ssum[c], v);
        atomicAdd(&ssq[c], q);
    }
    __syncthreads();
    if (tid < F2) {
        atomicAdd(&g_stat2[tid], ssum[tid]);
        atomicAdd(&g_stat2[F2 + tid], ssq[tid]);
    }
}

__global__ void k_params2(const float* __restrict__ g, const float* __restrict__ be) {
    int c = threadIdx.x;
    if (c < F2) {
        float inv = 1.0f / (float)MTOT;
        float mean = g_stat2[c] * inv;
        float var  = g_stat2[F2 + c] * inv - mean * mean;
        float rstd = rsqrtf(var + BN_EPS);
        float s = g[c] * rstd;
        g_st2[c]      = s;
        g_st2[F2 + c] = be[c] - mean * s;
    }
}

// ---------------- K13: GEMM3 ----------------
__global__ void __launch_bounds__(256) k_gemm3(const float* __restrict__ x1,
                                               const float* __restrict__ W3) {
    __shared__ float w3s[F2 * F3];
    __shared__ float s2[F2], t2[F2];
    int tid = threadIdx.x;
    if (tid < F2 * F3) w3s[tid] = W3[tid];
    if (tid < F2) { s2[tid] = g_st2[tid]; t2[tid] = g_st2[F2 + tid]; }
    __syncthreads();

    int row = blockIdx.x * blockDim.x + tid;
    if (row < MTOT) {
        float v[F2];
        float4 a = *(const float4*)(x1 + (size_t)row * F2);
        float4 b = *(const float4*)(x1 + (size_t)row * F2 + 4);
        v[0] = a.x; v[1] = a.y; v[2] = a.z; v[3] = a.w;
        v[4] = b.x; v[5] = b.y; v[6] = b.z; v[7] = b.w;
#pragma unroll
        for (int k = 0; k < F2; k++) v[k] = fmaxf(v[k], 0.f) * s2[k] + t2[k];
        float o0 = 0.f, o1 = 0.f, o2 = 0.f;
#pragma unroll
        for (int k = 0; k < F2; k++) {
            o0 += v[k] * w3s[k * F3 + 0];
            o1 += v[k] * w3s[k * F3 + 1];
            o2 += v[k] * w3s[k * F3 + 2];
        }
        g_xw3[(size_t)row * F3 + 0] = o0;
        g_xw3[(size_t)row * F3 + 1] = o1;
        g_xw3[(size_t)row * F3 + 2] = o2;
    }
}

// ---------------- K14: prop3 ----------------
__global__ void __launch_bounds__(256) k_prop3(const float* __restrict__ b3,
                                               float* __restrict__ out) {
    int gt = blockIdx.x * blockDim.x + threadIdx.x;
    int node = gt >> 3;
    int sub = gt & 7;
    int b = sub >> 2, c = sub & 3;
    if (node >= NN || c >= F3) return;
    int start = g_rowptr[node], end = g_rowptr[node + 1];
    const float* src = g_xw3 + (size_t)b * NN * F3 + c;
    float acc = 0.f;
    for (int e = start; e < end; e++) {
        acc += g_snorm[e] * src[(size_t)g_srow[e] * F3];
    }
    acc += b3[c];
    out[(size_t)(b * NN + node) * F3 + c] = acc;
}

// ---------------- host launcher ----------------
extern "C" void kernel_launch(void* const* d_in, const int* in_sizes, int n_in,
                              void* d_out, int out_size) {
    const float* x   = (const float*)d_in[0];
    const float* W1  = (const float*)d_in[1];
    const float* b1  = (const float*)d_in[2];
    const float* g1  = (const float*)d_in[3];
    const float* be1 = (const float*)d_in[4];
    const float* W2  = (const float*)d_in[5];
    const float* b2  = (const float*)d_in[6];
    const float* g2  = (const float*)d_in[7];
    const float* be2 = (const float*)d_in[8];
    const float* W3  = (const float*)d_in[9];
    const float* b3  = (const float*)d_in[10];
    const void*  ei  = d_in[11];

    float* out_p = (float*)d_out + OUT_OFF_OUT;
    float* x1_p  = (float*)d_out + OUT_OFF_X1;

    // graph prep
    k_zero<<<256, 256>>>();
    k_detect<<<1024, 256>>>((const unsigned int*)ei);
    k_build<<<1024, 256>>>(ei);
    k_scan_a<<<NBLK, SCAN_B>>>();
    k_scan_b<<<1, SCAN_B>>>();
    k_scan_c<<<NBLK, SCAN_B>>>();
    k_scatter<<<1024, 256>>>(ei);

    // layer 1
    k_gemm1<<<(MTOT + 63) / 64, 256>>>(x, W1);
    k_prop1<<<NN / 8, 256>>>(b1);
    k_params1<<<1, 64>>>(g1, be1);

    // layer 2
    k_gemm2<<<(MTOT + 31) / 32, 256>>>(W2);
    k_prop2<<<NN / 16, 256>>>(b2, x1_p);
    k_params2<<<1, 32>>>(g2, be2);

    // layer 3
    k_gemm3<<<(MTOT + 255) / 256, 256>>>(x1_p, W3);
    k_prop3<<<(NN * 8 + 255) / 256, 256>>>(b3, out_p);
}

// round 3
// speedup vs baseline: 1.7352x; 1.2817x over previous
#include <cuda_runtime.h>
#include <cstdint>
#include <cstddef>

#define NN   50000
#define EE   800000
#define BB   2
#define MTOT (BB*NN)      // 100000
#define ETOT (EE+NN)      // 850000
#define F0   216
#define F1   64
#define F2   8
#define F3   3
#define BN_EPS 1e-5f

#define OUT_OFF_OUT 0
#define OUT_OFF_X1  (MTOT*F3)   // 300000

#define SCAN_B 256
#define NBLK   ((NN + SCAN_B - 1) / SCAN_B)   // 196

// ---------------- device scratch ----------------
__device__ int   g_flag;               // 1 => int32 edge_index, 0 => int64
__device__ int   g_cnt[NN];
__device__ int   g_rowptr[NN + 1];
__device__ int   g_woff[NN];
__device__ float g_dinv[NN];
__device__ int   g_bsum[NBLK];
__device__ int   g_boff[NBLK];
__device__ int2  g_edge[ETOT];         // {src_row, float_bits(norm)}
__device__ float g_xw1[(size_t)MTOT * F1];
__device__ float g_h1 [(size_t)MTOT * F1];
__device__ float g_xw2[(size_t)MTOT * F2];
__device__ float g_xw3[(size_t)MTOT * F3];
__device__ float g_stat1[2 * F1];
__device__ float g_st1 [2 * F1];
__device__ float g_stat2[2 * F2];
__device__ float g_st2 [2 * F2];

// ---------------- helpers ----------------
__device__ __forceinline__ unsigned tf32_rna(float f) {
    unsigned r;
    asm("cvt.rna.tf32.f32 %0, %1;" : "=r"(r) : "f"(f));
    return r;
}
__device__ __forceinline__ void ldsm_x4(unsigned& r0, unsigned& r1, unsigned& r2, unsigned& r3,
                                        unsigned addr) {
    asm volatile("ldmatrix.sync.aligned.m8n8.x4.shared.b16 {%0,%1,%2,%3}, [%4];"
                 : "=r"(r0), "=r"(r1), "=r"(r2), "=r"(r3) : "r"(addr));
}
__device__ __forceinline__ void mma_tf32(float& d0, float& d1, float& d2, float& d3,
                                         unsigned a0, unsigned a1, unsigned a2, unsigned a3,
                                         unsigned b0, unsigned b1) {
    asm volatile("mma.sync.aligned.m16n8k8.row.col.f32.tf32.tf32.f32 "
                 "{%0,%1,%2,%3}, {%4,%5,%6,%7}, {%8,%9}, {%0,%1,%2,%3};"
                 : "+f"(d0), "+f"(d1), "+f"(d2), "+f"(d3)
                 : "r"(a0), "r"(a1), "r"(a2), "r"(a3), "r"(b0), "r"(b1));
}

// ---------------- K0: zero ----------------
__global__ void k_zero() {
    int i = blockIdx.x * blockDim.x + threadIdx.x;
    for (int j = i; j < NN; j += gridDim.x * blockDim.x) g_cnt[j] = 0;
    if (i == 0) g_flag = 0;
    if (i < 2 * F1) g_stat1[i] = 0.f;
    if (i < 2 * F2) g_stat2[i] = 0.f;
}

// ---------------- K1: dtype detect ----------------
__global__ void k_detect(const unsigned int* __restrict__ w) {
    int i = blockIdx.x * blockDim.x + threadIdx.x;
    for (int e = i; e < EE; e += gridDim.x * blockDim.x) {
        if (w[2 * e + 1] != 0u) { g_flag = 1; return; }
    }
}

// ---------------- K2: degree histogram ----------------
__global__ void k_build(const void* __restrict__ ei) {
    int i = blockIdx.x * blockDim.x + threadIdx.x;
    int f = g_flag;
    const int*       e32 = (const int*)ei;
    const long long* e64 = (const long long*)ei;
    for (int e = i; e < ETOT; e += gridDim.x * blockDim.x) {
        int c;
        if (e < EE) c = f ? e32[EE + e] : (int)e64[EE + e];
        else        c = e - EE;
        atomicAdd(&g_cnt[c], 1);
    }
}

// ---------------- scan: two-level ----------------
__global__ void k_scan_a() {
    __shared__ int sh[SCAN_B];
    int tid = threadIdx.x;
    int idx = blockIdx.x * SCAN_B + tid;
    sh[tid] = (idx < NN) ? g_cnt[idx] : 0;
    __syncthreads();
    for (int off = 128; off > 0; off >>= 1) {
        if (tid < off) sh[tid] += sh[tid + off];
        __syncthreads();
    }
    if (tid == 0) g_bsum[blockIdx.x] = sh[0];
}

__global__ void k_scan_b() {
    __shared__ int sh[SCAN_B];
    int tid = threadIdx.x;
    int v = (tid < NBLK) ? g_bsum[tid] : 0;
    sh[tid] = v;
    __syncthreads();
    for (int off = 1; off < SCAN_B; off <<= 1) {
        int t = (tid >= off) ? sh[tid - off] : 0;
        __syncthreads();
        sh[tid] += t;
        __syncthreads();
    }
    if (tid < NBLK) g_boff[tid] = sh[tid] - v;
}

__global__ void k_scan_c() {
    __shared__ int sh[SCAN_B];
    int tid = threadIdx.x;
    int idx = blockIdx.x * SCAN_B + tid;
    int cnt = (idx < NN) ? g_cnt[idx] : 0;
    sh[tid] = cnt;
    __syncthreads();
    for (int off = 1; off < SCAN_B; off <<= 1) {
        int t = (tid >= off) ? sh[tid - off] : 0;
        __syncthreads();
        sh[tid] += t;
        __syncthreads();
    }
    int off0 = g_boff[blockIdx.x] + sh[tid] - cnt;
    if (idx < NN) {
        g_rowptr[idx] = off0;
        g_woff[idx]   = off0;
        g_dinv[idx]   = rsqrtf((float)cnt);
        if (idx == NN - 1) g_rowptr[NN] = off0 + cnt;
    }
}

// ---------------- K4: scatter packed edge records ----------------
__global__ void k_scatter(const void* __restrict__ ei) {
    int i = blockIdx.x * blockDim.x + threadIdx.x;
    int f = g_flag;
    const int*       e32 = (const int*)ei;
    const long long* e64 = (const long long*)ei;
    for (int e = i; e < ETOT; e += gridDim.x * blockDim.x) {
        int r, c;
        if (e < EE) {
            if (f) { r = e32[e]; c = e32[EE + e]; }
            else   { r = (int)e64[e]; c = (int)e64[EE + e]; }
        } else {
            r = c = e - EE;
        }
        int p = atomicAdd(&g_woff[c], 1);
        g_edge[p] = make_int2(r, __float_as_int(g_dinv[r] * g_dinv[c]));
    }
}

// ---------------- K5: GEMM1 tf32 MMA: [MTOT,216]@[216,64] -> g_xw1 ----------------
// block: 256 thr = 8 warps; tile BM=128, BN=64; warp tile 32x32 (2 m16 x 4 n8)
#define AST 12   // padded floats per shared row (48B, conflict-free for ldmatrix)
__global__ void __launch_bounds__(256) k_gemm1(const float* __restrict__ A,
                                               const float* __restrict__ W) {
    __shared__ unsigned As[128 * AST];
    __shared__ unsigned Bs[64 * AST];
    int tid  = threadIdx.x;
    int lane = tid & 31;
    int warp = tid >> 5;
    int wm = warp >> 1;         // 0..3  -> rows wm*32
    int wn = warp & 1;          // 0..1  -> cols wn*32
    int row0 = blockIdx.x * 128;

    // global load coords (A): thread -> row tid>>1, k-quad (tid&1)*4
    int lrow = tid >> 1;
    int lkq  = (tid & 1) * 4;
    int garow = row0 + lrow;
    bool avalid = garow < MTOT;
    const float* aptr = A + (size_t)garow * F0 + lkq;

    // B load coords: k = tid>>5, n pair = (tid&31)*2
    int bk = tid >> 5;
    int bn = (tid & 31) * 2;

    // ldmatrix shared addresses (constant over loop)
    unsigned as_base = (unsigned)__cvta_generic_to_shared(As);
    unsigned bs_base = (unsigned)__cvta_generic_to_shared(Bs);
    int arow_l = ((lane >> 3) & 1) * 8 + (lane & 7);
    int acol_b = (lane >> 4) * 16;
    unsigned aaddr0 = as_base + (unsigned)((wm * 32 + arow_l) * (AST * 4) + acol_b);
    unsigned aaddr1 = aaddr0 + 16 * (AST * 4);
    int brow_l = (lane >> 4) * 8 + (lane & 7);
    int bcol_b = ((lane >> 3) & 1) * 16;
    unsigned baddr0 = bs_base + (unsigned)((wn * 32 + brow_l) * (AST * 4) + bcol_b);
    unsigned baddr1 = baddr0 + 16 * (AST * 4);

    float acc[2][4][4];
#pragma unroll
    for (int mi = 0; mi < 2; mi++)
#pragma unroll
        for (int ni = 0; ni < 4; ni++)
#pragma unroll
            for (int j = 0; j < 4; j++) acc[mi][ni][j] = 0.f;

    for (int k0 = 0; k0 < F0; k0 += 8) {
        float4 a = avalid ? *(const float4*)(aptr + k0) : make_float4(0.f, 0.f, 0.f, 0.f);
        unsigned* asw = &As[lrow * AST + lkq];
        asw[0] = tf32_rna(a.x); asw[1] = tf32_rna(a.y);
        asw[2] = tf32_rna(a.z); asw[3] = tf32_rna(a.w);
        float2 wv = *(const float2*)(W + (size_t)(k0 + bk) * F1 + bn);
        Bs[bn * AST + bk]       = tf32_rna(wv.x);
        Bs[(bn + 1) * AST + bk] = tf32_rna(wv.y);
        __syncthreads();

        unsigned a0[4], a1[4], b0[4], b1[4];
        ldsm_x4(a0[0], a0[1], a0[2], a0[3], aaddr0);
        ldsm_x4(a1[0], a1[1], a1[2], a1[3], aaddr1);
        ldsm_x4(b0[0], b0[1], b0[2], b0[3], baddr0);   // n-tiles 0,1 (b0,b1 each)
        ldsm_x4(b1[0], b1[1], b1[2], b1[3], baddr1);   // n-tiles 2,3

#pragma unroll
        for (int ni = 0; ni < 4; ni++) {
            unsigned bb0 = (ni < 2) ? b0[(ni & 1) * 2]     : b1[(ni & 1) * 2];
            unsigned bb1 = (ni < 2) ? b0[(ni & 1) * 2 + 1] : b1[(ni & 1) * 2 + 1];
            mma_tf32(acc[0][ni][0], acc[0][ni][1], acc[0][ni][2], acc[0][ni][3],
                     a0[0], a0[1], a0[2], a0[3], bb0, bb1);
            mma_tf32(acc[1][ni][0], acc[1][ni][1], acc[1][ni][2], acc[1][ni][3],
                     a1[0], a1[1], a1[2], a1[3], bb0, bb1);
        }
        __syncthreads();
    }

    // epilogue
    int cr = lane >> 2;            // 0..7
    int cc = (lane & 3) * 2;       // 0,2,4,6
#pragma unroll
    for (int mi = 0; mi < 2; mi++) {
        int rlo = row0 + wm * 32 + mi * 16 + cr;
        int rhi = rlo + 8;
#pragma unroll
        for (int ni = 0; ni < 4; ni++) {
            int col = wn * 32 + ni * 8 + cc;
            if (rlo < MTOT)
                *(float2*)&g_xw1[(size_t)rlo * F1 + col] = make_float2(acc[mi][ni][0], acc[mi][ni][1]);
            if (rhi < MTOT)
                *(float2*)&g_xw1[(size_t)rhi * F1 + col] = make_float2(acc[mi][ni][2], acc[mi][ni][3]);
        }
    }
}

// ---------------- K6: prop1 + bias + ReLU + fused BN stats ----------------
__global__ void __launch_bounds__(256) k_prop1(const float* __restrict__ b1) {
    __shared__ float ssum[F1];
    __shared__ float ssq [F1];
    int tid = threadIdx.x;
    if (tid < F1) { ssum[tid] = 0.f; ssq[tid] = 0.f; }
    __syncthreads();

    int gwarp = (blockIdx.x * blockDim.x + tid) >> 5;   // node id
    int lane  = tid & 31;
    int start = g_rowptr[gwarp], end = g_rowptr[gwarp + 1];
    int b  = lane >> 4;
    int c4 = (lane & 15) * 4;
    const float* src = g_xw1 + (size_t)b * NN * F1 + c4;
    float4 acc = make_float4(0.f, 0.f, 0.f, 0.f);

    int e = start;
    for (; e + 4 <= end; e += 4) {
        int2 p0 = g_edge[e], p1 = g_edge[e + 1], p2 = g_edge[e + 2], p3 = g_edge[e + 3];
        float4 v0 = *(const float4*)(src + (size_t)p0.x * F1);
        float4 v1 = *(const float4*)(src + (size_t)p1.x * F1);
        float4 v2 = *(const float4*)(src + (size_t)p2.x * F1);
        float4 v3 = *(const float4*)(src + (size_t)p3.x * F1);
        float w0 = __int_as_float(p0.y), w1 = __int_as_float(p1.y);
        float w2 = __int_as_float(p2.y), w3 = __int_as_float(p3.y);
        acc.x += w0 * v0.x + w1 * v1.x + w2 * v2.x + w3 * v3.x;
        acc.y += w0 * v0.y + w1 * v1.y + w2 * v2.y + w3 * v3.y;
        acc.z += w0 * v0.z + w1 * v1.z + w2 * v2.z + w3 * v3.z;
        acc.w += w0 * v0.w + w1 * v1.w + w2 * v2.w + w3 * v3.w;
    }
    for (; e < end; e++) {
        int2 p = g_edge[e];
        float w = __int_as_float(p.y);
        float4 v = *(const float4*)(src + (size_t)p.x * F1);
        acc.x += w * v.x; acc.y += w * v.y; acc.z += w * v.z; acc.w += w * v.w;
    }
    float4 bb = *(const float4*)(b1 + c4);
    acc.x = fmaxf(acc.x + bb.x, 0.f);
    acc.y = fmaxf(acc.y + bb.y, 0.f);
    acc.z = fmaxf(acc.z + bb.z, 0.f);
    acc.w = fmaxf(acc.w + bb.w, 0.f);
    *(float4*)(g_h1 + (size_t)(b * NN + gwarp) * F1 + c4) = acc;

    float s0 = acc.x, s1 = acc.y, s2 = acc.z, s3 = acc.w;
    float q0 = s0 * s0, q1 = s1 * s1, q2 = s2 * s2, q3 = s3 * s3;
    s0 += __shfl_xor_sync(0xffffffffu, s0, 16);
    s1 += __shfl_xor_sync(0xffffffffu, s1, 16);
    s2 += __shfl_xor_sync(0xffffffffu, s2, 16);
    s3 += __shfl_xor_sync(0xffffffffu, s3, 16);
    q0 += __shfl_xor_sync(0xffffffffu, q0, 16);
    q1 += __shfl_xor_sync(0xffffffffu, q1, 16);
    q2 += __shfl_xor_sync(0xffffffffu, q2, 16);
    q3 += __shfl_xor_sync(0xffffffffu, q3, 16);
    if (lane < 16) {
        atomicAdd(&ssum[c4 + 0], s0); atomicAdd(&ssq[c4 + 0], q0);
        atomicAdd(&ssum[c4 + 1], s1); atomicAdd(&ssq[c4 + 1], q1);
        atomicAdd(&ssum[c4 + 2], s2); atomicAdd(&ssq[c4 + 2], q2);
        atomicAdd(&ssum[c4 + 3], s3); atomicAdd(&ssq[c4 + 3], q3);
    }
    __syncthreads();
    if (tid < F1) {
        atomicAdd(&g_stat1[tid], ssum[tid]);
        atomicAdd(&g_stat1[F1 + tid], ssq[tid]);
    }
}

__global__ void k_params1(const float* __restrict__ g, const float* __restrict__ be) {
    int c = threadIdx.x;
    if (c < F1) {
        float inv = 1.0f / (float)MTOT;
        float mean = g_stat1[c] * inv;
        float var  = g_stat1[F1 + c] * inv - mean * mean;
        float rstd = rsqrtf(var + BN_EPS);
        float s = g[c] * rstd;
        g_st1[c]      = s;
        g_st1[F1 + c] = be[c] - mean * s;
    }
}

// ---------------- K9: GEMM2 with fused BN affine ----------------
__global__ void __launch_bounds__(256) k_gemm2(const float* __restrict__ W2) {
    __shared__ float tile[32][64];
    __shared__ float w2s[F1 * F2];
    __shared__ float ss[F1], tt[F1];
    int tid = threadIdx.x;
    if (tid < F1) { ss[tid] = g_st1[tid]; tt[tid] = g_st1[F1 + tid]; }
    w2s[tid] = W2[tid];
    w2s[tid + 256] = W2[tid + 256];
    __syncthreads();

    int row0 = blockIdx.x * 32;
    for (int i = tid; i < 32 * 64; i += 256) {
        int r = i >> 6, k = i & 63;
        float v = (row0 + r < MTOT) ? g_h1[(size_t)(row0 + r) * F1 + k] : 0.f;
        tile[r][k] = v * ss[k] + tt[k];
    }
    __syncthreads();

    int r = tid >> 3, c = tid & 7;
    float acc = 0.f;
#pragma unroll
    for (int k = 0; k < F1; k++) acc += tile[r][k] * w2s[k * F2 + c];
    if (row0 + r < MTOT) g_xw2[(size_t)(row0 + r) * F2 + c] = acc;
}

// ---------------- K10: prop2 + bias -> x1, fused stats over relu(x1) ----------------
__global__ void __launch_bounds__(256) k_prop2(const float* __restrict__ b2,
                                               float* __restrict__ x1out) {
    __shared__ float ssum[F2];
    __shared__ float ssq [F2];
    int tid = threadIdx.x;
    if (tid < F2) { ssum[tid] = 0.f; ssq[tid] = 0.f; }
    __syncthreads();

    int gt = blockIdx.x * blockDim.x + tid;
    int node = gt >> 4;
    int sub = gt & 15;
    int b = sub >> 3, c = sub & 7;
    int start = g_rowptr[node], end = g_rowptr[node + 1];
    const float* src = g_xw2 + (size_t)b * NN * F2 + c;
    float acc = 0.f;
    int e = start;
    for (; e + 4 <= end; e += 4) {
        int2 p0 = g_edge[e], p1 = g_edge[e + 1], p2 = g_edge[e + 2], p3 = g_edge[e + 3];
        acc += __int_as_float(p0.y) * src[(size_t)p0.x * F2]
             + __int_as_float(p1.y) * src[(size_t)p1.x * F2]
             + __int_as_float(p2.y) * src[(size_t)p2.x * F2]
             + __int_as_float(p3.y) * src[(size_t)p3.x * F2];
    }
    for (; e < end; e++) {
        int2 p = g_edge[e];
        acc += __int_as_float(p.y) * src[(size_t)p.x * F2];
    }
    acc += b2[c];
    x1out[(size_t)(b * NN + node) * F2 + c] = acc;

    float v = fmaxf(acc, 0.f);
    float q = v * v;
    v += __shfl_xor_sync(0xffffffffu, v, 16);
    q += __shfl_xor_sync(0xffffffffu, q, 16);
    v += __shfl_xor_sync(0xffffffffu, v, 8);
    q += __shfl_xor_sync(0xffffffffu, q, 8);
    if ((tid & 31) < 8) {
        atomicAdd(&ssum[c], v);
        atomicAdd(&ssq[c], q);
    }
    __syncthreads();
    if (tid < F2) {
        atomicAdd(&g_stat2[tid], ssum[tid]);
        atomicAdd(&g_stat2[F2 + tid], ssq[tid]);
    }
}

__global__ void k_params2(const float* __restrict__ g, const float* __restrict__ be) {
    int c = threadIdx.x;
    if (c < F2) {
        float inv = 1.0f / (float)MTOT;
        float mean = g_stat2[c] * inv;
        float var  = g_stat2[F2 + c] * inv - mean * mean;
        float rstd = rsqrtf(var + BN_EPS);
        float s = g[c] * rstd;
        g_st2[c]      = s;
        g_st2[F2 + c] = be[c] - mean * s;
    }
}

// ---------------- K13: GEMM3 ----------------
__global__ void __launch_bounds__(256) k_gemm3(const float* __restrict__ x1,
                                               const float* __restrict__ W3) {
    __shared__ float w3s[F2 * F3];
    __shared__ float s2[F2], t2[F2];
    int tid = threadIdx.x;
    if (tid < F2 * F3) w3s[tid] = W3[tid];
    if (tid < F2) { s2[tid] = g_st2[tid]; t2[tid] = g_st2[F2 + tid]; }
    __syncthreads();

    int row = blockIdx.x * blockDim.x + tid;
    if (row < MTOT) {
        float v[F2];
        float4 a = *(const float4*)(x1 + (size_t)row * F2);
        float4 b = *(const float4*)(x1 + (size_t)row * F2 + 4);
        v[0] = a.x; v[1] = a.y; v[2] = a.z; v[3] = a.w;
        v[4] = b.x; v[5] = b.y; v[6] = b.z; v[7] = b.w;
#pragma unroll
        for (int k = 0; k < F2; k++) v[k] = fmaxf(v[k], 0.f) * s2[k] + t2[k];
        float o0 = 0.f, o1 = 0.f, o2 = 0.f;
#pragma unroll
        for (int k = 0; k < F2; k++) {
            o0 += v[k] * w3s[k * F3 + 0];
            o1 += v[k] * w3s[k * F3 + 1];
            o2 += v[k] * w3s[k * F3 + 2];
        }
        g_xw3[(size_t)row * F3 + 0] = o0;
        g_xw3[(size_t)row * F3 + 1] = o1;
        g_xw3[(size_t)row * F3 + 2] = o2;
    }
}

// ---------------- K14: prop3 ----------------
__global__ void __launch_bounds__(256) k_prop3(const float* __restrict__ b3,
                                               float* __restrict__ out) {
    int gt = blockIdx.x * blockDim.x + threadIdx.x;
    int node = gt >> 3;
    int sub = gt & 7;
    int b = sub >> 2, c = sub & 3;
    if (node >= NN || c >= F3) return;
    int start = g_rowptr[node], end = g_rowptr[node + 1];
    const float* src = g_xw3 + (size_t)b * NN * F3 + c;
    float acc = 0.f;
    int e = start;
    for (; e + 4 <= end; e += 4) {
        int2 p0 = g_edge[e], p1 = g_edge[e + 1], p2 = g_edge[e + 2], p3 = g_edge[e + 3];
        acc += __int_as_float(p0.y) * src[(size_t)p0.x * F3]
             + __int_as_float(p1.y) * src[(size_t)p1.x * F3]
             + __int_as_float(p2.y) * src[(size_t)p2.x * F3]
             + __int_as_float(p3.y) * src[(size_t)p3.x * F3];
    }
    for (; e < end; e++) {
        int2 p = g_edge[e];
        acc += __int_as_float(p.y) * src[(size_t)p.x * F3];
    }
    acc += b3[c];
    out[(size_t)(b * NN + node) * F3 + c] = acc;
}

// ---------------- host launcher ----------------
extern "C" void kernel_launch(void* const* d_in, const int* in_sizes, int n_in,
                              void* d_out, int out_size) {
    const float* x   = (const float*)d_in[0];
    const float* W1  = (const float*)d_in[1];
    const float* b1  = (const float*)d_in[2];
    const float* g1  = (const float*)d_in[3];
    const float* be1 = (const float*)d_in[4];
    const float* W2  = (const float*)d_in[5];
    const float* b2  = (const float*)d_in[6];
    const float* g2  = (const float*)d_in[7];
    const float* be2 = (const float*)d_in[8];
    const float* W3  = (const float*)d_in[9];
    const float* b3  = (const float*)d_in[10];
    const void*  ei  = d_in[11];

    float* out_p = (float*)d_out + OUT_OFF_OUT;
    float* x1_p  = (float*)d_out + OUT_OFF_X1;

    // graph prep
    k_zero<<<256, 256>>>();
    k_detect<<<1024, 256>>>((const unsigned int*)ei);
    k_build<<<1024, 256>>>(ei);
    k_scan_a<<<NBLK, SCAN_B>>>();
    k_scan_b<<<1, SCAN_B>>>();
    k_scan_c<<<NBLK, SCAN_B>>>();
    k_scatter<<<1024, 256>>>(ei);

    // layer 1
    k_gemm1<<<(MTOT + 127) / 128, 256>>>(x, W1);
    k_prop1<<<NN / 8, 256>>>(b1);
    k_params1<<<1, 64>>>(g1, be1);

    // layer 2
    k_gemm2<<<(MTOT + 31) / 32, 256>>>(W2);
    k_prop2<<<NN / 16, 256>>>(b2, x1_p);
    k_params2<<<1, 32>>>(g2, be2);

    // layer 3
    k_gemm3<<<(MTOT + 255) / 256, 256>>>(x1_p, W3);
    k_prop3<<<(NN * 8 + 255) / 256, 256>>>(b3, out_p);
}